// round 12
// baseline (speedup 1.0000x reference)
#include <cuda_runtime.h>
#include <cuda_fp16.h>

// ---------------------------------------------------------------------------
// GCN 2-layer forward. Pull-based aggregation over fixed-stride ELL buckets
// (cap 64, single-pass build: no prefix scan). fp16 operand, HADD2 tree,
// fp32 master accumulator.
//   y1 = half( (x@W1) * rsqrt(deg+1) )
//   h  = relu( (y1[d] + sum y1[src]) * rsqrt(deg[d]+1) + b1 )
//   y2 = half( (h@W2) * rsqrt(deg+1) )
//   out= (y2[d] + sum y2[src]) * rsqrt(deg[d]+1) + b2
// Schedule:
//   main: memset deg/cur -> deg_count -> {evFork} GEMM1 {evY1} -> [evFill]
//         gather1(A) -> GEMM2(A) -> [evG1B] GEMM2(B) -> gather2
//   s2:   [evFork] fill_ell {evFill} -> [evY1] gather1(B) {evG1B}
// ---------------------------------------------------------------------------

#define NODES_MAX 100000
#define EDGES_MAX 1600000
#define FEAT_IN   128
#define FEAT      64
#define ELL_CAP   64

__device__ __half g_y1[(size_t)NODES_MAX * FEAT];
__device__ __half g_y2[(size_t)NODES_MAX * FEAT];
__device__ float  g_h [(size_t)NODES_MAX * FEAT];
__device__ int    g_deg[NODES_MAX];
__device__ int    g_cur[NODES_MAX];
__device__ int    g_ell[(size_t)NODES_MAX * ELL_CAP];

// ---------------------------------------------------------------------------
__device__ __forceinline__ int detect64(const int* __restrict__ ei) {
    int lane = threadIdx.x & 31;
    int v = __ldg(&ei[2 * lane + 1]);
    return (__ballot_sync(0xffffffffu, v != 0) == 0u) ? 1 : 0;
}

__global__ void deg_count_kernel(const int* __restrict__ ei, int* __restrict__ deg, int E) {
    int is64 = detect64(ei);
    int e0 = 4 * (blockIdx.x * blockDim.x + threadIdx.x);
    if (e0 >= E) return;
    if (e0 + 4 <= E) {
        if (is64) {
            const longlong2* p = (const longlong2*)ei + E / 2 + e0 / 2;
            longlong2 a = p[0], b = p[1];
            atomicAdd(&deg[(int)a.x], 1);
            atomicAdd(&deg[(int)a.y], 1);
            atomicAdd(&deg[(int)b.x], 1);
            atomicAdd(&deg[(int)b.y], 1);
        } else {
            int4 d4 = *(const int4*)(ei + E + e0);
            atomicAdd(&deg[d4.x], 1);
            atomicAdd(&deg[d4.y], 1);
            atomicAdd(&deg[d4.z], 1);
            atomicAdd(&deg[d4.w], 1);
        }
    } else {
        for (int e = e0; e < E; e++) {
            long long pos = (long long)E + e;
            int d = is64 ? ei[2 * pos] : ei[pos];
            atomicAdd(&deg[d], 1);
        }
    }
}

// Single-pass ELL fill: ell[d*64 + cur[d]++] = s. No scan needed.
__global__ void fill_ell_kernel(const int* __restrict__ ei, int* __restrict__ cur,
                                int* __restrict__ ell, int E) {
    int is64 = detect64(ei);
    int e0 = 4 * (blockIdx.x * blockDim.x + threadIdx.x);
    if (e0 >= E) return;
    int s[4], d[4];
    if (e0 + 4 <= E) {
        if (is64) {
            const longlong2* ps = (const longlong2*)ei + e0 / 2;
            const longlong2* pd = (const longlong2*)ei + E / 2 + e0 / 2;
            longlong2 sa = ps[0], sb = ps[1], da = pd[0], db = pd[1];
            s[0] = (int)sa.x; s[1] = (int)sa.y; s[2] = (int)sb.x; s[3] = (int)sb.y;
            d[0] = (int)da.x; d[1] = (int)da.y; d[2] = (int)db.x; d[3] = (int)db.y;
        } else {
            int4 s4 = *(const int4*)(ei + e0);
            int4 d4 = *(const int4*)(ei + E + e0);
            s[0] = s4.x; s[1] = s4.y; s[2] = s4.z; s[3] = s4.w;
            d[0] = d4.x; d[1] = d4.y; d[2] = d4.z; d[3] = d4.w;
        }
#pragma unroll
        for (int k = 0; k < 4; k++) {
            int pos = atomicAdd(&cur[d[k]], 1);
            if (pos < ELL_CAP) ell[(size_t)d[k] * ELL_CAP + pos] = s[k];
        }
    } else {
        for (int e = e0; e < E; e++) {
            int ss, dd;
            if (is64) {
                ss = ei[2 * (long long)e];
                dd = ei[2 * ((long long)E + e)];
            } else {
                ss = ei[e];
                dd = ei[(long long)E + e];
            }
            int pos = atomicAdd(&cur[dd], 1);
            if (pos < ELL_CAP) ell[(size_t)dd * ELL_CAP + pos] = ss;
        }
    }
}

// ---------------------------------------------------------------------------
// GEMM core + inline rsqrt(deg+1) scale + fp16 convert.
// ---------------------------------------------------------------------------
template <int K>
__global__ __launch_bounds__(256) void gemm_scale_h_kernel(
    const float* __restrict__ X, const float* __restrict__ W,
    const int* __restrict__ deg, __half* __restrict__ yh, int n, int base)
{
    constexpr int KC = 32;
    __shared__ __align__(16) float Xs[128][KC];
    __shared__ __align__(16) float Ws[KC][64];

    int tid = threadIdx.x;
    int cg  = tid & 15;
    int ng  = tid >> 4;
    int node0 = base + blockIdx.x * 128;

    float4 accv[8];
#pragma unroll
    for (int i = 0; i < 8; i++) accv[i] = make_float4(0.f, 0.f, 0.f, 0.f);

    for (int kc = 0; kc < K; kc += KC) {
#pragma unroll
        for (int l = 0; l < 4; l++) {
            int fi = tid + l * 256;
            int r  = fi >> 3;
            int c  = (fi & 7) << 2;
            int node = node0 + r;
            float4 v = make_float4(0.f, 0.f, 0.f, 0.f);
            if (node < n) v = *(const float4*)(X + (size_t)node * K + kc + c);
            *(float4*)(&Xs[r][c]) = v;
        }
#pragma unroll
        for (int l = 0; l < 2; l++) {
            int fi = tid + l * 256;
            int r  = fi >> 4;
            int c  = (fi & 15) << 2;
            *(float4*)(&Ws[r][c]) = *(const float4*)(W + (size_t)(kc + r) * 64 + c);
        }
        __syncthreads();

#pragma unroll
        for (int k4 = 0; k4 < KC; k4 += 4) {
            float4 wr[4];
#pragma unroll
            for (int kk = 0; kk < 4; kk++)
                wr[kk] = *(float4*)(&Ws[k4 + kk][cg << 2]);
#pragma unroll
            for (int i = 0; i < 8; i++) {
                float4 xq = *(float4*)(&Xs[ng + 16 * i][k4]);
                accv[i].x = fmaf(xq.x, wr[0].x, accv[i].x);
                accv[i].y = fmaf(xq.x, wr[0].y, accv[i].y);
                accv[i].z = fmaf(xq.x, wr[0].z, accv[i].z);
                accv[i].w = fmaf(xq.x, wr[0].w, accv[i].w);
                accv[i].x = fmaf(xq.y, wr[1].x, accv[i].x);
                accv[i].y = fmaf(xq.y, wr[1].y, accv[i].y);
                accv[i].z = fmaf(xq.y, wr[1].z, accv[i].z);
                accv[i].w = fmaf(xq.y, wr[1].w, accv[i].w);
                accv[i].x = fmaf(xq.z, wr[2].x, accv[i].x);
                accv[i].y = fmaf(xq.z, wr[2].y, accv[i].y);
                accv[i].z = fmaf(xq.z, wr[2].z, accv[i].z);
                accv[i].w = fmaf(xq.z, wr[2].w, accv[i].w);
                accv[i].x = fmaf(xq.w, wr[3].x, accv[i].x);
                accv[i].y = fmaf(xq.w, wr[3].y, accv[i].y);
                accv[i].z = fmaf(xq.w, wr[3].z, accv[i].z);
                accv[i].w = fmaf(xq.w, wr[3].w, accv[i].w);
            }
        }
        __syncthreads();
    }

#pragma unroll
    for (int i = 0; i < 8; i++) {
        int node = node0 + ng + 16 * i;
        if (node < n) {
            float di = rsqrtf((float)(deg[node] + 1));
            float4 v = accv[i];
            __half2 h0 = __floats2half2_rn(v.x * di, v.y * di);
            __half2 h1 = __floats2half2_rn(v.z * di, v.w * di);
            uint2 u;
            u.x = *reinterpret_cast<unsigned*>(&h0);
            u.y = *reinterpret_cast<unsigned*>(&h1);
            *(uint2*)(yh + (size_t)node * 64 + (cg << 2)) = u;
        }
    }
}

// ---------------------------------------------------------------------------
// Gather over ELL rows: 8 threads/node, uint4 payload, aligned int4 index
// loads (row base = node*64), 4-edge HADD2 tree, fp32 scalar tail.
// ---------------------------------------------------------------------------
__device__ __forceinline__ __half2 u2h(unsigned u) { return *reinterpret_cast<__half2*>(&u); }

__device__ __forceinline__ void acc_u4_f32(float* acc, uint4 v) {
    float2 a = __half22float2(u2h(v.x));
    float2 b = __half22float2(u2h(v.y));
    float2 c = __half22float2(u2h(v.z));
    float2 d = __half22float2(u2h(v.w));
    acc[0] += a.x; acc[1] += a.y; acc[2] += b.x; acc[3] += b.y;
    acc[4] += c.x; acc[5] += c.y; acc[6] += d.x; acc[7] += d.y;
}

template <bool RELU>
__global__ __launch_bounds__(256) void gather_kernel(
    const int* __restrict__ deg, const int* __restrict__ ell,
    const uint4* __restrict__ yh, const float* __restrict__ bias,
    float* __restrict__ out, int base, int count)
{
    int idx = blockIdx.x * blockDim.x + threadIdx.x;
    int nrel = idx >> 3;
    if (nrel >= count) return;
    int node = base + nrel;
    int c = idx & 7;                       // owns halves [8c, 8c+8)

    int dg  = deg[node];
    int end = (dg < ELL_CAP) ? dg : ELL_CAP;
    const int* row = ell + (size_t)node * ELL_CAP;   // 16B-aligned base

    float acc[8];
    {   // self-loop row: straight fp32 accumulate
        uint4 v = yh[(size_t)node * 8 + c];
        float2 a = __half22float2(u2h(v.x));
        float2 b = __half22float2(u2h(v.y));
        float2 cc = __half22float2(u2h(v.z));
        float2 d = __half22float2(u2h(v.w));
        acc[0] = a.x; acc[1] = a.y; acc[2] = b.x; acc[3] = b.y;
        acc[4] = cc.x; acc[5] = cc.y; acc[6] = d.x; acc[7] = d.y;
    }

    int j = 0;
    // 4-edge groups: aligned int4 index load + HADD2 tree, then fp32 add.
    for (; j + 4 <= end; j += 4) {
        int4 s4 = *(const int4*)(row + j);     // j multiple of 4, base aligned
        uint4 v0 = yh[(size_t)s4.x * 8 + c];
        uint4 v1 = yh[(size_t)s4.y * 8 + c];
        uint4 v2 = yh[(size_t)s4.z * 8 + c];
        uint4 v3 = yh[(size_t)s4.w * 8 + c];
        __half2 p0 = __hadd2(u2h(v0.x), u2h(v1.x));
        __half2 p1 = __hadd2(u2h(v0.y), u2h(v1.y));
        __half2 p2 = __hadd2(u2h(v0.z), u2h(v1.z));
        __half2 p3 = __hadd2(u2h(v0.w), u2h(v1.w));
        __half2 q0 = __hadd2(u2h(v2.x), u2h(v3.x));
        __half2 q1 = __hadd2(u2h(v2.y), u2h(v3.y));
        __half2 q2 = __hadd2(u2h(v2.z), u2h(v3.z));
        __half2 q3 = __hadd2(u2h(v2.w), u2h(v3.w));
        __half2 r0 = __hadd2(p0, q0);
        __half2 r1 = __hadd2(p1, q1);
        __half2 r2 = __hadd2(p2, q2);
        __half2 r3 = __hadd2(p3, q3);
        float2 f0 = __half22float2(r0);
        float2 f1 = __half22float2(r1);
        float2 f2 = __half22float2(r2);
        float2 f3 = __half22float2(r3);
        acc[0] += f0.x; acc[1] += f0.y; acc[2] += f1.x; acc[3] += f1.y;
        acc[4] += f2.x; acc[5] += f2.y; acc[6] += f3.x; acc[7] += f3.y;
    }
    // tail (<=3 edges): fp32 accumulate
    for (; j < end; j++) {
        uint4 v = yh[(size_t)row[j] * 8 + c];
        acc_u4_f32(acc, v);
    }

    float di = rsqrtf((float)(dg + 1));
    float4 bl = *(const float4*)(bias + c * 8);
    float4 bh = *(const float4*)(bias + c * 8 + 4);
    float4 r0, r1;
    r0.x = fmaf(acc[0], di, bl.x);
    r0.y = fmaf(acc[1], di, bl.y);
    r0.z = fmaf(acc[2], di, bl.z);
    r0.w = fmaf(acc[3], di, bl.w);
    r1.x = fmaf(acc[4], di, bh.x);
    r1.y = fmaf(acc[5], di, bh.y);
    r1.z = fmaf(acc[6], di, bh.z);
    r1.w = fmaf(acc[7], di, bh.w);
    if (RELU) {
        r0.x = fmaxf(r0.x, 0.f); r0.y = fmaxf(r0.y, 0.f);
        r0.z = fmaxf(r0.z, 0.f); r0.w = fmaxf(r0.w, 0.f);
        r1.x = fmaxf(r1.x, 0.f); r1.y = fmaxf(r1.y, 0.f);
        r1.z = fmaxf(r1.z, 0.f); r1.w = fmaxf(r1.w, 0.f);
    }
    float* po = out + (size_t)node * 64 + c * 8;
    *(float4*)po       = r0;
    *(float4*)(po + 4) = r1;
}

// ---------------------------------------------------------------------------
extern "C" void kernel_launch(void* const* d_in, const int* in_sizes, int n_in,
                              void* d_out, int out_size)
{
    const float* x  = (const float*)d_in[0];
    const int*   ei = (const int*)d_in[1];
    const float* W1 = (const float*)d_in[2];
    const float* b1 = (const float*)d_in[3];
    const float* W2 = (const float*)d_in[4];
    const float* b2 = (const float*)d_in[5];

    int n = in_sizes[0] / FEAT_IN;   // 100000
    int E = in_sizes[1] / 2;         // 1600000

    __half *y1, *y2;
    float *h;
    int *deg, *cur, *ell;
    cudaGetSymbolAddress((void**)&y1,  g_y1);
    cudaGetSymbolAddress((void**)&y2,  g_y2);
    cudaGetSymbolAddress((void**)&h,   g_h);
    cudaGetSymbolAddress((void**)&deg, g_deg);
    cudaGetSymbolAddress((void**)&cur, g_cur);
    cudaGetSymbolAddress((void**)&ell, g_ell);

    static cudaStream_t s2 = nullptr;
    static cudaEvent_t evFork = nullptr, evFill = nullptr, evY1 = nullptr, evG1B = nullptr;
    static int overlap_ok = -1;
    if (overlap_ok < 0) {
        overlap_ok = 1;
        if (cudaStreamCreateWithFlags(&s2, cudaStreamNonBlocking) != cudaSuccess) overlap_ok = 0;
        if (overlap_ok && cudaEventCreateWithFlags(&evFork, cudaEventDisableTiming) != cudaSuccess) overlap_ok = 0;
        if (overlap_ok && cudaEventCreateWithFlags(&evFill, cudaEventDisableTiming) != cudaSuccess) overlap_ok = 0;
        if (overlap_ok && cudaEventCreateWithFlags(&evY1, cudaEventDisableTiming) != cudaSuccess) overlap_ok = 0;
        if (overlap_ok && cudaEventCreateWithFlags(&evG1B, cudaEventDisableTiming) != cudaSuccess) overlap_ok = 0;
    }
    cudaStream_t sc = overlap_ok ? s2 : (cudaStream_t)0;

    const int T = 256;
    int eb4 = (E / 4 + T - 1) / T;

    int nh = ((n / 2 + 127) / 128) * 128;
    if (nh > n) nh = n;
    int gbA = (nh * 8 + T - 1) / T;
    int gbB = ((n - nh) * 8 + T - 1) / T;
    int gbF = (n * 8 + T - 1) / T;
    int mbA = (nh + 127) / 128;
    int mbB = (n - nh + 127) / 128;

    // ---- Prefix (main): deg (GEMM1 epilogue dependency) ----
    cudaMemsetAsync(deg, 0, (size_t)n * sizeof(int), 0);
    cudaMemsetAsync(cur, 0, (size_t)n * sizeof(int), 0);
    deg_count_kernel<<<eb4, T>>>(ei, deg, E);

    // ---- Fork: ELL fill on s2 (no scan!), GEMM1 on main ----
    if (overlap_ok) {
        cudaEventRecord(evFork, 0);
        cudaStreamWaitEvent(sc, evFork, 0);
    }
    fill_ell_kernel<<<eb4, T, 0, sc>>>(ei, cur, ell, E);
    if (overlap_ok) cudaEventRecord(evFill, sc);

    gemm_scale_h_kernel<128><<<(n + 127) / 128, 256>>>(x, W1, deg, y1, n, 0);
    if (overlap_ok) cudaEventRecord(evY1, 0);

    // ---- s2: gather1(B) once y1 ready (fill already done on s2 order) ----
    if (overlap_ok && gbB > 0) {
        cudaStreamWaitEvent(sc, evY1, 0);
        gather_kernel<true><<<gbB, T, 0, sc>>>(deg, ell, (const uint4*)y1,
                                               b1, h, nh, n - nh);
        cudaEventRecord(evG1B, sc);
    }

    // ---- main: gather1(A) after fill ----
    if (overlap_ok) cudaStreamWaitEvent(0, evFill, 0);
    gather_kernel<true><<<gbA, T>>>(deg, ell, (const uint4*)y1,
                                    b1, h, 0, nh);
    if (!overlap_ok && gbB > 0)
        gather_kernel<true><<<gbB, T>>>(deg, ell, (const uint4*)y1,
                                        b1, h, nh, n - nh);

    // ---- GEMM2(A) (overlaps gather1(B) tail), then GEMM2(B) ----
    gemm_scale_h_kernel<64><<<mbA, 256>>>(h, W2, deg, y2, n, 0);
    if (overlap_ok) cudaStreamWaitEvent(0, evG1B, 0);
    if (mbB > 0)
        gemm_scale_h_kernel<64><<<mbB, 256>>>(h, W2, deg, y2, n, nh);

    // ---- final gather ----
    gather_kernel<false><<<gbF, T>>>(deg, ell, (const uint4*)y2,
                                     b2, (float*)d_out, 0, n);
}

// round 13
// speedup vs baseline: 1.0362x; 1.0362x over previous
#include <cuda_runtime.h>
#include <cuda_fp16.h>

// ---------------------------------------------------------------------------
// GCN 2-layer forward, pull-based CSR gather, fp16 operand with HADD2 tree.
// R10 structure (best: 151.6us) + unroll-8 gather main loop for 2x MLP.
//   y1 = half( (x@W1) * rsqrt(deg+1) )
//   h  = relu( (y1[d] + sum y1[src]) * rsqrt(deg[d]+1) + b1 )
//   y2 = half( (h@W2) * rsqrt(deg+1) )
//   out= (y2[d] + sum y2[src]) * rsqrt(deg[d]+1) + b2
// Schedule:
//   main: memset deg -> deg_count -> {evFork} GEMM1 {evY1} -> [evJoin]
//         gather1(A) -> GEMM2(A) -> [evG1B] GEMM2(B) -> gather2
//   s2:   [evFork] scanA -> scanB -> fill {evJoin} -> [evY1] gather1(B) {evG1B}
// ---------------------------------------------------------------------------

#define NODES_MAX 100000
#define EDGES_MAX 1600000
#define FEAT_IN   128
#define FEAT      64

__device__ __half g_y1[(size_t)NODES_MAX * FEAT];
__device__ __half g_y2[(size_t)NODES_MAX * FEAT];
__device__ float  g_h [(size_t)NODES_MAX * FEAT];
__device__ int    g_deg [NODES_MAX];
__device__ int    g_off [NODES_MAX + 1];
__device__ int    g_cur [NODES_MAX];
__device__ int    g_csr [EDGES_MAX];
__device__ int    g_bsum[256];

// ---------------------------------------------------------------------------
__device__ __forceinline__ int detect64(const int* __restrict__ ei) {
    int lane = threadIdx.x & 31;
    int v = __ldg(&ei[2 * lane + 1]);
    return (__ballot_sync(0xffffffffu, v != 0) == 0u) ? 1 : 0;
}

__global__ void deg_count_kernel(const int* __restrict__ ei, int* __restrict__ deg, int E) {
    int is64 = detect64(ei);
    int e0 = 4 * (blockIdx.x * blockDim.x + threadIdx.x);
    if (e0 >= E) return;
    if (e0 + 4 <= E) {
        if (is64) {
            const longlong2* p = (const longlong2*)ei + E / 2 + e0 / 2;
            longlong2 a = p[0], b = p[1];
            atomicAdd(&deg[(int)a.x], 1);
            atomicAdd(&deg[(int)a.y], 1);
            atomicAdd(&deg[(int)b.x], 1);
            atomicAdd(&deg[(int)b.y], 1);
        } else {
            int4 d4 = *(const int4*)(ei + E + e0);
            atomicAdd(&deg[d4.x], 1);
            atomicAdd(&deg[d4.y], 1);
            atomicAdd(&deg[d4.z], 1);
            atomicAdd(&deg[d4.w], 1);
        }
    } else {
        for (int e = e0; e < E; e++) {
            long long pos = (long long)E + e;
            int d = is64 ? ei[2 * pos] : ei[pos];
            atomicAdd(&deg[d], 1);
        }
    }
}

// ---------------------------------------------------------------------------
__device__ __forceinline__ int block_exscan(int v, int* total) {
    __shared__ int wsum[32];
    int lane = threadIdx.x & 31, wid = threadIdx.x >> 5;
    int nw = blockDim.x >> 5;
    int inc = v;
#pragma unroll
    for (int o = 1; o < 32; o <<= 1) {
        int t = __shfl_up_sync(0xffffffffu, inc, o);
        if (lane >= o) inc += t;
    }
    if (lane == 31) wsum[wid] = inc;
    __syncthreads();
    if (wid == 0) {
        int ws = (lane < nw) ? wsum[lane] : 0;
#pragma unroll
        for (int o = 1; o < 32; o <<= 1) {
            int t = __shfl_up_sync(0xffffffffu, ws, o);
            if (lane >= o) ws += t;
        }
        wsum[lane] = ws;
    }
    __syncthreads();
    int woff = (wid == 0) ? 0 : wsum[wid - 1];
    *total = wsum[nw - 1];
    return woff + inc - v;
}

__global__ __launch_bounds__(1024) void scanA_kernel(
    const int* __restrict__ deg, int* __restrict__ off,
    int* __restrict__ bsum, int n)
{
    int i = blockIdx.x * blockDim.x + threadIdx.x;
    int v = (i < n) ? deg[i] : 0;
    int tot;
    int ex = block_exscan(v, &tot);
    if (i < n) off[i] = ex;
    if (threadIdx.x == 0) bsum[blockIdx.x] = tot;
}

__global__ __launch_bounds__(1024) void scanB_kernel(
    int* __restrict__ off, const int* __restrict__ bsum,
    int* __restrict__ cur, int n, int nb, int E)
{
    __shared__ int sb[128];
    int t = threadIdx.x, b = blockIdx.x;
    if (t < 128) sb[t] = (t < nb && t < b) ? bsum[t] : 0;
    __syncthreads();
#pragma unroll
    for (int o = 64; o > 0; o >>= 1) {
        if (t < o) sb[t] += sb[t + o];
        __syncthreads();
    }
    int pre = sb[0];
    int i = b * blockDim.x + t;
    if (i < n) {
        int o = off[i] + pre;
        off[i] = o;
        cur[i] = o;
    }
    if (b == 0 && t == 0) off[n] = E;
}

__global__ void fill_kernel(const int* __restrict__ ei, int* __restrict__ cur,
                            int* __restrict__ csr, int E) {
    int is64 = detect64(ei);
    int e0 = 4 * (blockIdx.x * blockDim.x + threadIdx.x);
    if (e0 >= E) return;
    int s[4], d[4];
    if (e0 + 4 <= E) {
        if (is64) {
            const longlong2* ps = (const longlong2*)ei + e0 / 2;
            const longlong2* pd = (const longlong2*)ei + E / 2 + e0 / 2;
            longlong2 sa = ps[0], sb = ps[1], da = pd[0], db = pd[1];
            s[0] = (int)sa.x; s[1] = (int)sa.y; s[2] = (int)sb.x; s[3] = (int)sb.y;
            d[0] = (int)da.x; d[1] = (int)da.y; d[2] = (int)db.x; d[3] = (int)db.y;
        } else {
            int4 s4 = *(const int4*)(ei + e0);
            int4 d4 = *(const int4*)(ei + E + e0);
            s[0] = s4.x; s[1] = s4.y; s[2] = s4.z; s[3] = s4.w;
            d[0] = d4.x; d[1] = d4.y; d[2] = d4.z; d[3] = d4.w;
        }
#pragma unroll
        for (int k = 0; k < 4; k++) {
            int pos = atomicAdd(&cur[d[k]], 1);
            csr[pos] = s[k];
        }
    } else {
        for (int e = e0; e < E; e++) {
            int ss, dd;
            if (is64) {
                ss = ei[2 * (long long)e];
                dd = ei[2 * ((long long)E + e)];
            } else {
                ss = ei[e];
                dd = ei[(long long)E + e];
            }
            int pos = atomicAdd(&cur[dd], 1);
            csr[pos] = ss;
        }
    }
}

// ---------------------------------------------------------------------------
// GEMM core + inline rsqrt(deg+1) scale + fp16 convert.
// ---------------------------------------------------------------------------
template <int K>
__global__ __launch_bounds__(256) void gemm_scale_h_kernel(
    const float* __restrict__ X, const float* __restrict__ W,
    const int* __restrict__ deg, __half* __restrict__ yh, int n, int base)
{
    constexpr int KC = 32;
    __shared__ __align__(16) float Xs[128][KC];
    __shared__ __align__(16) float Ws[KC][64];

    int tid = threadIdx.x;
    int cg  = tid & 15;
    int ng  = tid >> 4;
    int node0 = base + blockIdx.x * 128;

    float4 accv[8];
#pragma unroll
    for (int i = 0; i < 8; i++) accv[i] = make_float4(0.f, 0.f, 0.f, 0.f);

    for (int kc = 0; kc < K; kc += KC) {
#pragma unroll
        for (int l = 0; l < 4; l++) {
            int fi = tid + l * 256;
            int r  = fi >> 3;
            int c  = (fi & 7) << 2;
            int node = node0 + r;
            float4 v = make_float4(0.f, 0.f, 0.f, 0.f);
            if (node < n) v = *(const float4*)(X + (size_t)node * K + kc + c);
            *(float4*)(&Xs[r][c]) = v;
        }
#pragma unroll
        for (int l = 0; l < 2; l++) {
            int fi = tid + l * 256;
            int r  = fi >> 4;
            int c  = (fi & 15) << 2;
            *(float4*)(&Ws[r][c]) = *(const float4*)(W + (size_t)(kc + r) * 64 + c);
        }
        __syncthreads();

#pragma unroll
        for (int k4 = 0; k4 < KC; k4 += 4) {
            float4 wr[4];
#pragma unroll
            for (int kk = 0; kk < 4; kk++)
                wr[kk] = *(float4*)(&Ws[k4 + kk][cg << 2]);
#pragma unroll
            for (int i = 0; i < 8; i++) {
                float4 xq = *(float4*)(&Xs[ng + 16 * i][k4]);
                accv[i].x = fmaf(xq.x, wr[0].x, accv[i].x);
                accv[i].y = fmaf(xq.x, wr[0].y, accv[i].y);
                accv[i].z = fmaf(xq.x, wr[0].z, accv[i].z);
                accv[i].w = fmaf(xq.x, wr[0].w, accv[i].w);
                accv[i].x = fmaf(xq.y, wr[1].x, accv[i].x);
                accv[i].y = fmaf(xq.y, wr[1].y, accv[i].y);
                accv[i].z = fmaf(xq.y, wr[1].z, accv[i].z);
                accv[i].w = fmaf(xq.y, wr[1].w, accv[i].w);
                accv[i].x = fmaf(xq.z, wr[2].x, accv[i].x);
                accv[i].y = fmaf(xq.z, wr[2].y, accv[i].y);
                accv[i].z = fmaf(xq.z, wr[2].z, accv[i].z);
                accv[i].w = fmaf(xq.z, wr[2].w, accv[i].w);
                accv[i].x = fmaf(xq.w, wr[3].x, accv[i].x);
                accv[i].y = fmaf(xq.w, wr[3].y, accv[i].y);
                accv[i].z = fmaf(xq.w, wr[3].z, accv[i].z);
                accv[i].w = fmaf(xq.w, wr[3].w, accv[i].w);
            }
        }
        __syncthreads();
    }

#pragma unroll
    for (int i = 0; i < 8; i++) {
        int node = node0 + ng + 16 * i;
        if (node < n) {
            float di = rsqrtf((float)(deg[node] + 1));
            float4 v = accv[i];
            __half2 h0 = __floats2half2_rn(v.x * di, v.y * di);
            __half2 h1 = __floats2half2_rn(v.z * di, v.w * di);
            uint2 u;
            u.x = *reinterpret_cast<unsigned*>(&h0);
            u.y = *reinterpret_cast<unsigned*>(&h1);
            *(uint2*)(yh + (size_t)node * 64 + (cg << 2)) = u;
        }
    }
}

// ---------------------------------------------------------------------------
// Gather: 8 threads/node, uint4 payload. Main loop handles 8 edges per
// iteration (8 independent payload loads in flight -> 2x MLP), reduced by a
// 3-level HADD2 tree; 4-edge and scalar fp32 tails. Scalar index loads
// (csr row starts not 16B-aligned).
// ---------------------------------------------------------------------------
__device__ __forceinline__ __half2 u2h(unsigned u) { return *reinterpret_cast<__half2*>(&u); }

__device__ __forceinline__ void acc_u4_f32(float* acc, uint4 v) {
    float2 a = __half22float2(u2h(v.x));
    float2 b = __half22float2(u2h(v.y));
    float2 c = __half22float2(u2h(v.z));
    float2 d = __half22float2(u2h(v.w));
    acc[0] += a.x; acc[1] += a.y; acc[2] += b.x; acc[3] += b.y;
    acc[4] += c.x; acc[5] += c.y; acc[6] += d.x; acc[7] += d.y;
}

template <bool RELU>
__global__ __launch_bounds__(256) void gather_kernel(
    const int* __restrict__ deg, const int* __restrict__ off,
    const int* __restrict__ csr, const uint4* __restrict__ yh,
    const float* __restrict__ bias, float* __restrict__ out,
    int base, int count)
{
    int idx = blockIdx.x * blockDim.x + threadIdx.x;
    int nrel = idx >> 3;
    if (nrel >= count) return;
    int node = base + nrel;
    int c = idx & 7;                       // owns halves [8c, 8c+8)

    int j   = off[node];
    int end = off[node + 1];

    float acc[8];
    {   // self-loop row: straight fp32 accumulate
        uint4 v = yh[(size_t)node * 8 + c];
        float2 a = __half22float2(u2h(v.x));
        float2 b = __half22float2(u2h(v.y));
        float2 cc = __half22float2(u2h(v.z));
        float2 d = __half22float2(u2h(v.w));
        acc[0] = a.x; acc[1] = a.y; acc[2] = b.x; acc[3] = b.y;
        acc[4] = cc.x; acc[5] = cc.y; acc[6] = d.x; acc[7] = d.y;
    }

    // 8-edge groups: 8 payload loads in flight, 3-level HADD2 tree.
    for (; j + 8 <= end; j += 8) {
        int s0 = csr[j],     s1 = csr[j + 1], s2 = csr[j + 2], s3 = csr[j + 3];
        int s4 = csr[j + 4], s5 = csr[j + 5], s6 = csr[j + 6], s7 = csr[j + 7];
        uint4 v0 = yh[(size_t)s0 * 8 + c];
        uint4 v1 = yh[(size_t)s1 * 8 + c];
        uint4 v2 = yh[(size_t)s2 * 8 + c];
        uint4 v3 = yh[(size_t)s3 * 8 + c];
        uint4 v4 = yh[(size_t)s4 * 8 + c];
        uint4 v5 = yh[(size_t)s5 * 8 + c];
        uint4 v6 = yh[(size_t)s6 * 8 + c];
        uint4 v7 = yh[(size_t)s7 * 8 + c];
        // level 1: 4 pairs
        __half2 a0 = __hadd2(u2h(v0.x), u2h(v1.x));
        __half2 a1 = __hadd2(u2h(v0.y), u2h(v1.y));
        __half2 a2 = __hadd2(u2h(v0.z), u2h(v1.z));
        __half2 a3 = __hadd2(u2h(v0.w), u2h(v1.w));
        __half2 b0 = __hadd2(u2h(v2.x), u2h(v3.x));
        __half2 b1 = __hadd2(u2h(v2.y), u2h(v3.y));
        __half2 b2 = __hadd2(u2h(v2.z), u2h(v3.z));
        __half2 b3 = __hadd2(u2h(v2.w), u2h(v3.w));
        __half2 c0 = __hadd2(u2h(v4.x), u2h(v5.x));
        __half2 c1 = __hadd2(u2h(v4.y), u2h(v5.y));
        __half2 c2 = __hadd2(u2h(v4.z), u2h(v5.z));
        __half2 c3 = __hadd2(u2h(v4.w), u2h(v5.w));
        __half2 d0 = __hadd2(u2h(v6.x), u2h(v7.x));
        __half2 d1 = __hadd2(u2h(v6.y), u2h(v7.y));
        __half2 d2 = __hadd2(u2h(v6.z), u2h(v7.z));
        __half2 d3 = __hadd2(u2h(v6.w), u2h(v7.w));
        // level 2
        __half2 e0 = __hadd2(a0, b0);
        __half2 e1 = __hadd2(a1, b1);
        __half2 e2 = __hadd2(a2, b2);
        __half2 e3 = __hadd2(a3, b3);
        __half2 f0 = __hadd2(c0, d0);
        __half2 f1 = __hadd2(c1, d1);
        __half2 f2 = __hadd2(c2, d2);
        __half2 f3 = __hadd2(c3, d3);
        // level 3
        __half2 g0 = __hadd2(e0, f0);
        __half2 g1 = __hadd2(e1, f1);
        __half2 g2 = __hadd2(e2, f2);
        __half2 g3 = __hadd2(e3, f3);
        float2 w0 = __half22float2(g0);
        float2 w1 = __half22float2(g1);
        float2 w2 = __half22float2(g2);
        float2 w3 = __half22float2(g3);
        acc[0] += w0.x; acc[1] += w0.y; acc[2] += w1.x; acc[3] += w1.y;
        acc[4] += w2.x; acc[5] += w2.y; acc[6] += w3.x; acc[7] += w3.y;
    }
    // 4-edge group: 2-level HADD2 tree.
    if (j + 4 <= end) {
        int s0 = csr[j], s1 = csr[j + 1], s2 = csr[j + 2], s3 = csr[j + 3];
        j += 4;
        uint4 v0 = yh[(size_t)s0 * 8 + c];
        uint4 v1 = yh[(size_t)s1 * 8 + c];
        uint4 v2 = yh[(size_t)s2 * 8 + c];
        uint4 v3 = yh[(size_t)s3 * 8 + c];
        __half2 p0 = __hadd2(u2h(v0.x), u2h(v1.x));
        __half2 p1 = __hadd2(u2h(v0.y), u2h(v1.y));
        __half2 p2 = __hadd2(u2h(v0.z), u2h(v1.z));
        __half2 p3 = __hadd2(u2h(v0.w), u2h(v1.w));
        __half2 q0 = __hadd2(u2h(v2.x), u2h(v3.x));
        __half2 q1 = __hadd2(u2h(v2.y), u2h(v3.y));
        __half2 q2 = __hadd2(u2h(v2.z), u2h(v3.z));
        __half2 q3 = __hadd2(u2h(v2.w), u2h(v3.w));
        __half2 r0 = __hadd2(p0, q0);
        __half2 r1 = __hadd2(p1, q1);
        __half2 r2 = __hadd2(p2, q2);
        __half2 r3 = __hadd2(p3, q3);
        float2 f0 = __half22float2(r0);
        float2 f1 = __half22float2(r1);
        float2 f2 = __half22float2(r2);
        float2 f3 = __half22float2(r3);
        acc[0] += f0.x; acc[1] += f0.y; acc[2] += f1.x; acc[3] += f1.y;
        acc[4] += f2.x; acc[5] += f2.y; acc[6] += f3.x; acc[7] += f3.y;
    }
    // scalar tail: fp32 accumulate (no extra fp16 rounding)
    for (; j < end; j++) {
        uint4 v = yh[(size_t)csr[j] * 8 + c];
        acc_u4_f32(acc, v);
    }

    float di = rsqrtf((float)(deg[node] + 1));
    float4 bl = *(const float4*)(bias + c * 8);
    float4 bh = *(const float4*)(bias + c * 8 + 4);
    float4 r0, r1;
    r0.x = fmaf(acc[0], di, bl.x);
    r0.y = fmaf(acc[1], di, bl.y);
    r0.z = fmaf(acc[2], di, bl.z);
    r0.w = fmaf(acc[3], di, bl.w);
    r1.x = fmaf(acc[4], di, bh.x);
    r1.y = fmaf(acc[5], di, bh.y);
    r1.z = fmaf(acc[6], di, bh.z);
    r1.w = fmaf(acc[7], di, bh.w);
    if (RELU) {
        r0.x = fmaxf(r0.x, 0.f); r0.y = fmaxf(r0.y, 0.f);
        r0.z = fmaxf(r0.z, 0.f); r0.w = fmaxf(r0.w, 0.f);
        r1.x = fmaxf(r1.x, 0.f); r1.y = fmaxf(r1.y, 0.f);
        r1.z = fmaxf(r1.z, 0.f); r1.w = fmaxf(r1.w, 0.f);
    }
    float* po = out + (size_t)node * 64 + c * 8;
    *(float4*)po       = r0;
    *(float4*)(po + 4) = r1;
}

// ---------------------------------------------------------------------------
extern "C" void kernel_launch(void* const* d_in, const int* in_sizes, int n_in,
                              void* d_out, int out_size)
{
    const float* x  = (const float*)d_in[0];
    const int*   ei = (const int*)d_in[1];
    const float* W1 = (const float*)d_in[2];
    const float* b1 = (const float*)d_in[3];
    const float* W2 = (const float*)d_in[4];
    const float* b2 = (const float*)d_in[5];

    int n = in_sizes[0] / FEAT_IN;   // 100000
    int E = in_sizes[1] / 2;         // 1600000

    __half *y1, *y2;
    float *h;
    int *deg, *off, *cur, *csr, *bsum;
    cudaGetSymbolAddress((void**)&y1,   g_y1);
    cudaGetSymbolAddress((void**)&y2,   g_y2);
    cudaGetSymbolAddress((void**)&h,    g_h);
    cudaGetSymbolAddress((void**)&deg,  g_deg);
    cudaGetSymbolAddress((void**)&off,  g_off);
    cudaGetSymbolAddress((void**)&cur,  g_cur);
    cudaGetSymbolAddress((void**)&csr,  g_csr);
    cudaGetSymbolAddress((void**)&bsum, g_bsum);

    static cudaStream_t s2 = nullptr;
    static cudaEvent_t evFork = nullptr, evJoin = nullptr, evY1 = nullptr, evG1B = nullptr;
    static int overlap_ok = -1;
    if (overlap_ok < 0) {
        overlap_ok = 1;
        if (cudaStreamCreateWithFlags(&s2, cudaStreamNonBlocking) != cudaSuccess) overlap_ok = 0;
        if (overlap_ok && cudaEventCreateWithFlags(&evFork, cudaEventDisableTiming) != cudaSuccess) overlap_ok = 0;
        if (overlap_ok && cudaEventCreateWithFlags(&evJoin, cudaEventDisableTiming) != cudaSuccess) overlap_ok = 0;
        if (overlap_ok && cudaEventCreateWithFlags(&evY1, cudaEventDisableTiming) != cudaSuccess) overlap_ok = 0;
        if (overlap_ok && cudaEventCreateWithFlags(&evG1B, cudaEventDisableTiming) != cudaSuccess) overlap_ok = 0;
    }
    cudaStream_t sc = overlap_ok ? s2 : (cudaStream_t)0;

    const int T = 256;
    int eb4 = (E / 4 + T - 1) / T;
    int nbs = (n + 1023) / 1024;

    // node halves (multiple of 128 for GEMM tiles)
    int nh = ((n / 2 + 127) / 128) * 128;
    if (nh > n) nh = n;
    int gbA = (nh * 8 + T - 1) / T;
    int gbB = ((n - nh) * 8 + T - 1) / T;
    int gbF = (n * 8 + T - 1) / T;
    int mbA = (nh + 127) / 128;
    int mbB = (n - nh + 127) / 128;

    // ---- Prefix (main): deg ----
    cudaMemsetAsync(deg, 0, (size_t)n * sizeof(int), 0);
    deg_count_kernel<<<eb4, T>>>(ei, deg, E);

    // ---- Fork: scan+fill on s2 ----
    if (overlap_ok) {
        cudaEventRecord(evFork, 0);
        cudaStreamWaitEvent(sc, evFork, 0);
    }
    scanA_kernel<<<nbs, 1024, 0, sc>>>(deg, off, bsum, n);
    scanB_kernel<<<nbs, 1024, 0, sc>>>(off, bsum, cur, n, nbs, E);
    fill_kernel<<<eb4, T, 0, sc>>>(ei, cur, csr, E);
    if (overlap_ok) cudaEventRecord(evJoin, sc);

    // ---- GEMM1 on main (concurrent with scan+fill) ----
    gemm_scale_h_kernel<128><<<(n + 127) / 128, 256>>>(x, W1, deg, y1, n, 0);
    if (overlap_ok) cudaEventRecord(evY1, 0);

    // ---- s2: gather1(B) once y1 ready (runs concurrent with gather1(A)) ----
    if (overlap_ok && gbB > 0) {
        cudaStreamWaitEvent(sc, evY1, 0);
        gather_kernel<true><<<gbB, T, 0, sc>>>(deg, off, csr, (const uint4*)y1,
                                               b1, h, nh, n - nh);
        cudaEventRecord(evG1B, sc);
    }

    // ---- main: gather1(A) after fill ----
    if (overlap_ok) cudaStreamWaitEvent(0, evJoin, 0);
    gather_kernel<true><<<gbA, T>>>(deg, off, csr, (const uint4*)y1,
                                    b1, h, 0, nh);
    if (!overlap_ok && gbB > 0)
        gather_kernel<true><<<gbB, T>>>(deg, off, csr, (const uint4*)y1,
                                        b1, h, nh, n - nh);

    // ---- GEMM2(A) (overlaps gather1(B) tail), then GEMM2(B) ----
    gemm_scale_h_kernel<64><<<mbA, 256>>>(h, W2, deg, y2, n, 0);
    if (overlap_ok) cudaStreamWaitEvent(0, evG1B, 0);
    if (mbB > 0)
        gemm_scale_h_kernel<64><<<mbB, 256>>>(h, W2, deg, y2, n, nh);

    // ---- final gather ----
    gather_kernel<false><<<gbF, T>>>(deg, off, csr, (const uint4*)y2,
                                     b2, (float*)d_out, 0, n);
}

// round 16
// speedup vs baseline: 1.2781x; 1.2335x over previous
#include <cuda_runtime.h>
#include <cuda_fp16.h>
#include <cstdint>

// ---------------------------------------------------------------------------
// GCN 2-layer forward, pull-based CSR gather (R10 structure, best 151.6us),
// with tensor-core GEMMs: 3-term fp16-split HMMA (Ahi*Whi + Alo*Whi + Ahi*Wlo,
// fp32 accum) — fp32-grade precision at tensor-core speed.
//   y1 = half( (x@W1) * rsqrt(deg+1) )
//   h  = relu( (y1[d] + sum y1[src]) * rsqrt(deg[d]+1) + b1 )
//   y2 = half( (h@W2) * rsqrt(deg+1) )
//   out= (y2[d] + sum y2[src]) * rsqrt(deg[d]+1) + b2
// Schedule:
//   main: wconv -> memset deg -> deg_count -> {evFork} GEMM1 {evY1} ->
//         [evJoin] gather1(A) -> GEMM2(A) -> [evG1B] GEMM2(B) -> gather2
//   s2:   [evFork] scanA -> scanB -> fill {evJoin} -> [evY1] gather1(B) {evG1B}
// ---------------------------------------------------------------------------

#define NODES_MAX 100000
#define EDGES_MAX 1600000
#define FEAT_IN   128
#define FEAT      64

__device__ __half g_y1[(size_t)NODES_MAX * FEAT];
__device__ __half g_y2[(size_t)NODES_MAX * FEAT];
__device__ float  g_h [(size_t)NODES_MAX * FEAT];
__device__ int    g_deg [NODES_MAX];
__device__ int    g_off [NODES_MAX + 1];
__device__ int    g_cur [NODES_MAX];
__device__ int    g_csr [EDGES_MAX];
__device__ int    g_bsum[256];
__device__ __half g_w1hi[FEAT_IN * FEAT], g_w1lo[FEAT_IN * FEAT];
__device__ __half g_w2hi[FEAT * FEAT],    g_w2lo[FEAT * FEAT];

// ---------------------------------------------------------------------------
__device__ __forceinline__ int detect64(const int* __restrict__ ei) {
    int lane = threadIdx.x & 31;
    int v = __ldg(&ei[2 * lane + 1]);
    return (__ballot_sync(0xffffffffu, v != 0) == 0u) ? 1 : 0;
}

// Split W1/W2 into fp16 hi/lo once per call.
__global__ void wconv_kernel(const float* __restrict__ W1, const float* __restrict__ W2,
                             __half* __restrict__ w1hi, __half* __restrict__ w1lo,
                             __half* __restrict__ w2hi, __half* __restrict__ w2lo)
{
    int i = blockIdx.x * blockDim.x + threadIdx.x;
    if (i < FEAT_IN * FEAT) {
        float w = W1[i];
        __half h = __float2half(w);
        w1hi[i] = h;
        w1lo[i] = __float2half(w - __half2float(h));
    }
    if (i < FEAT * FEAT) {
        float w = W2[i];
        __half h = __float2half(w);
        w2hi[i] = h;
        w2lo[i] = __float2half(w - __half2float(h));
    }
}

__global__ void deg_count_kernel(const int* __restrict__ ei, int* __restrict__ deg, int E) {
    int is64 = detect64(ei);
    int e0 = 4 * (blockIdx.x * blockDim.x + threadIdx.x);
    if (e0 >= E) return;
    if (e0 + 4 <= E) {
        if (is64) {
            const longlong2* p = (const longlong2*)ei + E / 2 + e0 / 2;
            longlong2 a = p[0], b = p[1];
            atomicAdd(&deg[(int)a.x], 1);
            atomicAdd(&deg[(int)a.y], 1);
            atomicAdd(&deg[(int)b.x], 1);
            atomicAdd(&deg[(int)b.y], 1);
        } else {
            int4 d4 = *(const int4*)(ei + E + e0);
            atomicAdd(&deg[d4.x], 1);
            atomicAdd(&deg[d4.y], 1);
            atomicAdd(&deg[d4.z], 1);
            atomicAdd(&deg[d4.w], 1);
        }
    } else {
        for (int e = e0; e < E; e++) {
            long long pos = (long long)E + e;
            int d = is64 ? ei[2 * pos] : ei[pos];
            atomicAdd(&deg[d], 1);
        }
    }
}

// ---------------------------------------------------------------------------
__device__ __forceinline__ int block_exscan(int v, int* total) {
    __shared__ int wsum[32];
    int lane = threadIdx.x & 31, wid = threadIdx.x >> 5;
    int nw = blockDim.x >> 5;
    int inc = v;
#pragma unroll
    for (int o = 1; o < 32; o <<= 1) {
        int t = __shfl_up_sync(0xffffffffu, inc, o);
        if (lane >= o) inc += t;
    }
    if (lane == 31) wsum[wid] = inc;
    __syncthreads();
    if (wid == 0) {
        int ws = (lane < nw) ? wsum[lane] : 0;
#pragma unroll
        for (int o = 1; o < 32; o <<= 1) {
            int t = __shfl_up_sync(0xffffffffu, ws, o);
            if (lane >= o) ws += t;
        }
        wsum[lane] = ws;
    }
    __syncthreads();
    int woff = (wid == 0) ? 0 : wsum[wid - 1];
    *total = wsum[nw - 1];
    return woff + inc - v;
}

__global__ __launch_bounds__(1024) void scanA_kernel(
    const int* __restrict__ deg, int* __restrict__ off,
    int* __restrict__ bsum, int n)
{
    int i = blockIdx.x * blockDim.x + threadIdx.x;
    int v = (i < n) ? deg[i] : 0;
    int tot;
    int ex = block_exscan(v, &tot);
    if (i < n) off[i] = ex;
    if (threadIdx.x == 0) bsum[blockIdx.x] = tot;
}

__global__ __launch_bounds__(1024) void scanB_kernel(
    int* __restrict__ off, const int* __restrict__ bsum,
    int* __restrict__ cur, int n, int nb, int E)
{
    __shared__ int sb[128];
    int t = threadIdx.x, b = blockIdx.x;
    if (t < 128) sb[t] = (t < nb && t < b) ? bsum[t] : 0;
    __syncthreads();
#pragma unroll
    for (int o = 64; o > 0; o >>= 1) {
        if (t < o) sb[t] += sb[t + o];
        __syncthreads();
    }
    int pre = sb[0];
    int i = b * blockDim.x + t;
    if (i < n) {
        int o = off[i] + pre;
        off[i] = o;
        cur[i] = o;
    }
    if (b == 0 && t == 0) off[n] = E;
}

__global__ void fill_kernel(const int* __restrict__ ei, int* __restrict__ cur,
                            int* __restrict__ csr, int E) {
    int is64 = detect64(ei);
    int e0 = 4 * (blockIdx.x * blockDim.x + threadIdx.x);
    if (e0 >= E) return;
    int s[4], d[4];
    if (e0 + 4 <= E) {
        if (is64) {
            const longlong2* ps = (const longlong2*)ei + e0 / 2;
            const longlong2* pd = (const longlong2*)ei + E / 2 + e0 / 2;
            longlong2 sa = ps[0], sb = ps[1], da = pd[0], db = pd[1];
            s[0] = (int)sa.x; s[1] = (int)sa.y; s[2] = (int)sb.x; s[3] = (int)sb.y;
            d[0] = (int)da.x; d[1] = (int)da.y; d[2] = (int)db.x; d[3] = (int)db.y;
        } else {
            int4 s4 = *(const int4*)(ei + e0);
            int4 d4 = *(const int4*)(ei + E + e0);
            s[0] = s4.x; s[1] = s4.y; s[2] = s4.z; s[3] = s4.w;
            d[0] = d4.x; d[1] = d4.y; d[2] = d4.z; d[3] = d4.w;
        }
#pragma unroll
        for (int k = 0; k < 4; k++) {
            int pos = atomicAdd(&cur[d[k]], 1);
            csr[pos] = s[k];
        }
    } else {
        for (int e = e0; e < E; e++) {
            int ss, dd;
            if (is64) {
                ss = ei[2 * (long long)e];
                dd = ei[2 * ((long long)E + e)];
            } else {
                ss = ei[e];
                dd = ei[(long long)E + e];
            }
            int pos = atomicAdd(&cur[dd], 1);
            csr[pos] = ss;
        }
    }
}

// ---------------------------------------------------------------------------
// Tensor-core GEMM, 3-term fp16 split, fp32 accum, fused rsqrt(deg+1) scale
// + fp16 convert. Block: 128 rows x 64 cols, 8 warps (16 rows each).
// ---------------------------------------------------------------------------
__device__ __forceinline__ unsigned sptr(const void* p) {
    return (unsigned)__cvta_generic_to_shared(p);
}
__device__ __forceinline__ unsigned packh(__half a, __half b) {
    __half2 h = __halves2half2(a, b);
    return *reinterpret_cast<unsigned*>(&h);
}
__device__ __forceinline__ void ldm_x4(unsigned* r, unsigned addr) {
    asm volatile("ldmatrix.sync.aligned.m8n8.x4.shared.b16 {%0,%1,%2,%3}, [%4];"
                 : "=r"(r[0]), "=r"(r[1]), "=r"(r[2]), "=r"(r[3]) : "r"(addr));
}
__device__ __forceinline__ void ldm_x2t(unsigned* r, unsigned addr) {
    asm volatile("ldmatrix.sync.aligned.m8n8.x2.trans.shared.b16 {%0,%1}, [%2];"
                 : "=r"(r[0]), "=r"(r[1]) : "r"(addr));
}
__device__ __forceinline__ void mma16816(float* c, const unsigned* a, const unsigned* b) {
    asm volatile("mma.sync.aligned.m16n8k16.row.col.f32.f16.f16.f32 "
                 "{%0,%1,%2,%3}, {%4,%5,%6,%7}, {%8,%9}, {%0,%1,%2,%3};"
                 : "+f"(c[0]), "+f"(c[1]), "+f"(c[2]), "+f"(c[3])
                 : "r"(a[0]), "r"(a[1]), "r"(a[2]), "r"(a[3]), "r"(b[0]), "r"(b[1]));
}

template <int K>
__global__ __launch_bounds__(256) void gemm_tc_kernel(
    const float* __restrict__ A, const __half* __restrict__ Whi,
    const __half* __restrict__ Wlo, const int* __restrict__ deg,
    __half* __restrict__ yh, int n, int base)
{
    constexpr int KC = 32;
    constexpr int AS = 40;   // A smem row stride (halves): 80B, LDSM conflict-free
    constexpr int WS = 72;   // W smem row stride (halves): 144B
    __shared__ __align__(16) __half Ahi_s[128 * AS];
    __shared__ __align__(16) __half Alo_s[128 * AS];
    __shared__ __align__(16) __half Whi_s[KC * WS];
    __shared__ __align__(16) __half Wlo_s[KC * WS];

    int tid  = threadIdx.x;
    int warp = tid >> 5;
    int lane = tid & 31;
    int node0 = base + blockIdx.x * 128;
    int warpRow = warp * 16;

    float acc[8][4];
#pragma unroll
    for (int i = 0; i < 8; i++)
#pragma unroll
        for (int j = 0; j < 4; j++) acc[i][j] = 0.f;

    for (int kc = 0; kc < K; kc += KC) {
        // A chunk: 128x32 fp32 -> hi/lo fp16 smem (split during load)
#pragma unroll
        for (int l = 0; l < 4; l++) {
            int fi = tid + l * 256;
            int r  = fi >> 3;
            int cb = (fi & 7) << 2;
            int node = node0 + r;
            float4 v = make_float4(0.f, 0.f, 0.f, 0.f);
            if (node < n) v = *(const float4*)(A + (size_t)node * K + kc + cb);
            __half h0 = __float2half(v.x), h1 = __float2half(v.y);
            __half h2 = __float2half(v.z), h3 = __float2half(v.w);
            __half l0 = __float2half(v.x - __half2float(h0));
            __half l1 = __float2half(v.y - __half2float(h1));
            __half l2 = __float2half(v.z - __half2float(h2));
            __half l3 = __float2half(v.w - __half2float(h3));
            uint2 uh, ul;
            uh.x = packh(h0, h1); uh.y = packh(h2, h3);
            ul.x = packh(l0, l1); ul.y = packh(l2, l3);
            *(uint2*)(Ahi_s + r * AS + cb) = uh;
            *(uint2*)(Alo_s + r * AS + cb) = ul;
        }
        // W chunk: 32x64 halves (pre-split in gmem)
        {
            int r = tid >> 3;
            int q = (tid & 7) << 3;
            *(uint4*)(Whi_s + r * WS + q) = *(const uint4*)(Whi + (size_t)(kc + r) * 64 + q);
            *(uint4*)(Wlo_s + r * WS + q) = *(const uint4*)(Wlo + (size_t)(kc + r) * 64 + q);
        }
        __syncthreads();

#pragma unroll
        for (int kt = 0; kt < 2; kt++) {
            unsigned ahi[4], alo[4];
            int arow = warpRow + (lane & 15);
            int acol = kt * 16 + ((lane >> 4) << 3);
            ldm_x4(ahi, sptr(Ahi_s + arow * AS + acol));
            ldm_x4(alo, sptr(Alo_s + arow * AS + acol));
            int krow = kt * 16 + (lane & 15);
#pragma unroll
            for (int nt = 0; nt < 8; nt++) {
                unsigned bhi[2], blo[2];
                ldm_x2t(bhi, sptr(Whi_s + krow * WS + nt * 8));
                ldm_x2t(blo, sptr(Wlo_s + krow * WS + nt * 8));
                mma16816(acc[nt], ahi, bhi);
                mma16816(acc[nt], alo, bhi);
                mma16816(acc[nt], ahi, blo);
            }
        }
        __syncthreads();
    }

    // epilogue: scale by rsqrt(deg+1), convert to fp16, store
    int g = lane >> 2, t = lane & 3;
    int r0 = node0 + warpRow + g;
    int r1 = r0 + 8;
    float di0 = (r0 < n) ? rsqrtf((float)(deg[r0] + 1)) : 0.f;
    float di1 = (r1 < n) ? rsqrtf((float)(deg[r1] + 1)) : 0.f;
#pragma unroll
    for (int nt = 0; nt < 8; nt++) {
        int col = nt * 8 + 2 * t;
        if (r0 < n) {
            __half2 hv = __floats2half2_rn(acc[nt][0] * di0, acc[nt][1] * di0);
            *(__half2*)(yh + (size_t)r0 * 64 + col) = hv;
        }
        if (r1 < n) {
            __half2 hv = __floats2half2_rn(acc[nt][2] * di1, acc[nt][3] * di1);
            *(__half2*)(yh + (size_t)r1 * 64 + col) = hv;
        }
    }
}

// ---------------------------------------------------------------------------
// Gather (R10 exact): 8 threads/node, uint4 payload, 4-edge HADD2 tree,
// fp32 master accumulator, scalar index loads.
// ---------------------------------------------------------------------------
__device__ __forceinline__ __half2 u2h(unsigned u) { return *reinterpret_cast<__half2*>(&u); }

__device__ __forceinline__ void acc_u4_f32(float* acc, uint4 v) {
    float2 a = __half22float2(u2h(v.x));
    float2 b = __half22float2(u2h(v.y));
    float2 c = __half22float2(u2h(v.z));
    float2 d = __half22float2(u2h(v.w));
    acc[0] += a.x; acc[1] += a.y; acc[2] += b.x; acc[3] += b.y;
    acc[4] += c.x; acc[5] += c.y; acc[6] += d.x; acc[7] += d.y;
}

template <bool RELU>
__global__ __launch_bounds__(256) void gather_kernel(
    const int* __restrict__ deg, const int* __restrict__ off,
    const int* __restrict__ csr, const uint4* __restrict__ yh,
    const float* __restrict__ bias, float* __restrict__ out,
    int base, int count)
{
    int idx = blockIdx.x * blockDim.x + threadIdx.x;
    int nrel = idx >> 3;
    if (nrel >= count) return;
    int node = base + nrel;
    int c = idx & 7;

    int j   = off[node];
    int end = off[node + 1];

    float acc[8];
    {
        uint4 v = yh[(size_t)node * 8 + c];
        float2 a = __half22float2(u2h(v.x));
        float2 b = __half22float2(u2h(v.y));
        float2 cc = __half22float2(u2h(v.z));
        float2 d = __half22float2(u2h(v.w));
        acc[0] = a.x; acc[1] = a.y; acc[2] = b.x; acc[3] = b.y;
        acc[4] = cc.x; acc[5] = cc.y; acc[6] = d.x; acc[7] = d.y;
    }

    for (; j + 4 <= end; j += 4) {
        int s0 = csr[j], s1 = csr[j + 1], s2 = csr[j + 2], s3 = csr[j + 3];
        uint4 v0 = yh[(size_t)s0 * 8 + c];
        uint4 v1 = yh[(size_t)s1 * 8 + c];
        uint4 v2 = yh[(size_t)s2 * 8 + c];
        uint4 v3 = yh[(size_t)s3 * 8 + c];
        __half2 p0 = __hadd2(u2h(v0.x), u2h(v1.x));
        __half2 p1 = __hadd2(u2h(v0.y), u2h(v1.y));
        __half2 p2 = __hadd2(u2h(v0.z), u2h(v1.z));
        __half2 p3 = __hadd2(u2h(v0.w), u2h(v1.w));
        __half2 q0 = __hadd2(u2h(v2.x), u2h(v3.x));
        __half2 q1 = __hadd2(u2h(v2.y), u2h(v3.y));
        __half2 q2 = __hadd2(u2h(v2.z), u2h(v3.z));
        __half2 q3 = __hadd2(u2h(v2.w), u2h(v3.w));
        __half2 r0 = __hadd2(p0, q0);
        __half2 r1 = __hadd2(p1, q1);
        __half2 r2 = __hadd2(p2, q2);
        __half2 r3 = __hadd2(p3, q3);
        float2 f0 = __half22float2(r0);
        float2 f1 = __half22float2(r1);
        float2 f2 = __half22float2(r2);
        float2 f3 = __half22float2(r3);
        acc[0] += f0.x; acc[1] += f0.y; acc[2] += f1.x; acc[3] += f1.y;
        acc[4] += f2.x; acc[5] += f2.y; acc[6] += f3.x; acc[7] += f3.y;
    }
    for (; j < end; j++) {
        uint4 v = yh[(size_t)csr[j] * 8 + c];
        acc_u4_f32(acc, v);
    }

    float di = rsqrtf((float)(deg[node] + 1));
    float4 bl = *(const float4*)(bias + c * 8);
    float4 bh = *(const float4*)(bias + c * 8 + 4);
    float4 r0, r1;
    r0.x = fmaf(acc[0], di, bl.x);
    r0.y = fmaf(acc[1], di, bl.y);
    r0.z = fmaf(acc[2], di, bl.z);
    r0.w = fmaf(acc[3], di, bl.w);
    r1.x = fmaf(acc[4], di, bh.x);
    r1.y = fmaf(acc[5], di, bh.y);
    r1.z = fmaf(acc[6], di, bh.z);
    r1.w = fmaf(acc[7], di, bh.w);
    if (RELU) {
        r0.x = fmaxf(r0.x, 0.f); r0.y = fmaxf(r0.y, 0.f);
        r0.z = fmaxf(r0.z, 0.f); r0.w = fmaxf(r0.w, 0.f);
        r1.x = fmaxf(r1.x, 0.f); r1.y = fmaxf(r1.y, 0.f);
        r1.z = fmaxf(r1.z, 0.f); r1.w = fmaxf(r1.w, 0.f);
    }
    float* po = out + (size_t)node * 64 + c * 8;
    *(float4*)po       = r0;
    *(float4*)(po + 4) = r1;
}

// ---------------------------------------------------------------------------
extern "C" void kernel_launch(void* const* d_in, const int* in_sizes, int n_in,
                              void* d_out, int out_size)
{
    const float* x  = (const float*)d_in[0];
    const int*   ei = (const int*)d_in[1];
    const float* W1 = (const float*)d_in[2];
    const float* b1 = (const float*)d_in[3];
    const float* W2 = (const float*)d_in[4];
    const float* b2 = (const float*)d_in[5];

    int n = in_sizes[0] / FEAT_IN;   // 100000
    int E = in_sizes[1] / 2;         // 1600000

    __half *y1, *y2, *w1hi, *w1lo, *w2hi, *w2lo;
    float *h;
    int *deg, *off, *cur, *csr, *bsum;
    cudaGetSymbolAddress((void**)&y1,   g_y1);
    cudaGetSymbolAddress((void**)&y2,   g_y2);
    cudaGetSymbolAddress((void**)&h,    g_h);
    cudaGetSymbolAddress((void**)&deg,  g_deg);
    cudaGetSymbolAddress((void**)&off,  g_off);
    cudaGetSymbolAddress((void**)&cur,  g_cur);
    cudaGetSymbolAddress((void**)&csr,  g_csr);
    cudaGetSymbolAddress((void**)&bsum, g_bsum);
    cudaGetSymbolAddress((void**)&w1hi, g_w1hi);
    cudaGetSymbolAddress((void**)&w1lo, g_w1lo);
    cudaGetSymbolAddress((void**)&w2hi, g_w2hi);
    cudaGetSymbolAddress((void**)&w2lo, g_w2lo);

    static cudaStream_t s2 = nullptr;
    static cudaEvent_t evFork = nullptr, evJoin = nullptr, evY1 = nullptr, evG1B = nullptr;
    static int overlap_ok = -1;
    if (overlap_ok < 0) {
        overlap_ok = 1;
        if (cudaStreamCreateWithFlags(&s2, cudaStreamNonBlocking) != cudaSuccess) overlap_ok = 0;
        if (overlap_ok && cudaEventCreateWithFlags(&evFork, cudaEventDisableTiming) != cudaSuccess) overlap_ok = 0;
        if (overlap_ok && cudaEventCreateWithFlags(&evJoin, cudaEventDisableTiming) != cudaSuccess) overlap_ok = 0;
        if (overlap_ok && cudaEventCreateWithFlags(&evY1, cudaEventDisableTiming) != cudaSuccess) overlap_ok = 0;
        if (overlap_ok && cudaEventCreateWithFlags(&evG1B, cudaEventDisableTiming) != cudaSuccess) overlap_ok = 0;
    }
    cudaStream_t sc = overlap_ok ? s2 : (cudaStream_t)0;

    const int T = 256;
    int eb4 = (E / 4 + T - 1) / T;
    int nbs = (n + 1023) / 1024;

    int nh = ((n / 2 + 127) / 128) * 128;
    if (nh > n) nh = n;
    int gbA = (nh * 8 + T - 1) / T;
    int gbB = ((n - nh) * 8 + T - 1) / T;
    int gbF = (n * 8 + T - 1) / T;
    int mbA = (nh + 127) / 128;
    int mbB = (n - nh + 127) / 128;

    // ---- Prefix (main): W split, deg ----
    wconv_kernel<<<(FEAT_IN * FEAT + T - 1) / T, T>>>(W1, W2, w1hi, w1lo, w2hi, w2lo);
    cudaMemsetAsync(deg, 0, (size_t)n * sizeof(int), 0);
    deg_count_kernel<<<eb4, T>>>(ei, deg, E);

    // ---- Fork: scan+fill on s2 ----
    if (overlap_ok) {
        cudaEventRecord(evFork, 0);
        cudaStreamWaitEvent(sc, evFork, 0);
    }
    scanA_kernel<<<nbs, 1024, 0, sc>>>(deg, off, bsum, n);
    scanB_kernel<<<nbs, 1024, 0, sc>>>(off, bsum, cur, n, nbs, E);
    fill_kernel<<<eb4, T, 0, sc>>>(ei, cur, csr, E);
    if (overlap_ok) cudaEventRecord(evJoin, sc);

    // ---- GEMM1 (tensor core) on main ----
    gemm_tc_kernel<128><<<(n + 127) / 128, 256>>>(x, w1hi, w1lo, deg, y1, n, 0);
    if (overlap_ok) cudaEventRecord(evY1, 0);

    // ---- s2: gather1(B) once y1 ready ----
    if (overlap_ok && gbB > 0) {
        cudaStreamWaitEvent(sc, evY1, 0);
        gather_kernel<true><<<gbB, T, 0, sc>>>(deg, off, csr, (const uint4*)y1,
                                               b1, h, nh, n - nh);
        cudaEventRecord(evG1B, sc);
    }

    // ---- main: gather1(A) after fill ----
    if (overlap_ok) cudaStreamWaitEvent(0, evJoin, 0);
    gather_kernel<true><<<gbA, T>>>(deg, off, csr, (const uint4*)y1,
                                    b1, h, 0, nh);
    if (!overlap_ok && gbB > 0)
        gather_kernel<true><<<gbB, T>>>(deg, off, csr, (const uint4*)y1,
                                        b1, h, nh, n - nh);

    // ---- GEMM2(A) tensor core (overlaps gather1(B) tail), then GEMM2(B) ----
    gemm_tc_kernel<64><<<mbA, 256>>>(h, w2hi, w2lo, deg, y2, n, 0);
    if (overlap_ok) cudaStreamWaitEvent(0, evG1B, 0);
    if (mbB > 0)
        gemm_tc_kernel<64><<<mbB, 256>>>(h, w2hi, w2lo, deg, y2, n, nh);

    // ---- final gather ----
    gather_kernel<false><<<gbF, T>>>(deg, off, csr, (const uint4*)y2,
                                     b2, (float*)d_out, 0, n);
}